// round 7
// baseline (speedup 1.0000x reference)
#include <cuda_runtime.h>

// Guided filter, fully fused, SMEM-free warp-sliding (round-2 skeleton).
// One warp = 32-lane column band (28 stored outputs, 2-lane halo per side),
// slides down CHUNK_H rows. Deltas vs round 2:
//  - stage-1 h-sums use 4 shuffles/row (x,y neighbors only); hxy/hxx rebuilt
//    from the same shuffled neighbors via FMA (-4 SHFL/step).
//  - interior chunks (all but the last) run a guard-free inner loop: no row
//    bounds checks, unconditional pointer increments. Warp-uniform branch.
// Replication: stage 1 via clamped lane columns / clamped prologue rows,
// stage 2 via pl/pr selects at cols 0/1023 and ring copies at rows 0/1023.

#define W 1024
#define H 1024
#define EPSF 1e-6f
#define C9 (1.0f / 9.0f)

#define OUTC 28
#define BANDS 37                            // ceil(1024/28)
#define CHUNK_H 128
#define CHUNKS (H / CHUNK_H)                // 8
#define WPB 8                               // 256 threads
#define UNITS (24 * BANDS * CHUNKS)         // 7104 warps
#define NBLOCKS (UNITS / WPB)               // 888 blocks (1 wave @ 6/SM)

__global__ __launch_bounds__(256) void gf_kernel(const float* __restrict__ x,
                                                 const float* __restrict__ y,
                                                 float* __restrict__ out)
{
    const int wid  = threadIdx.x >> 5;
    const int lane = threadIdx.x & 31;
    const int g    = blockIdx.x * WPB + wid;

    const int plane = g / (BANDS * CHUNKS);
    const int rem   = g - plane * (BANDS * CHUNKS);
    const int band  = rem / CHUNKS;
    const int chunk = rem - band * CHUNKS;

    const int cbase = band * OUTC - 2;
    const int icr   = cbase + lane;                 // raw column of this lane
    const int ic    = min(max(icr, 0), W - 1);      // clamped load column
    const int r0    = chunk * CHUNK_H;

    const bool pl = (icr == 0);                     // stage-2 left replication
    const bool pr = (icr == W - 1);                 // stage-2 right replication
    const bool do_store = (lane >= 2) && (lane <= 29) && (icr >= 0) && (icr < W);

    const size_t pb = (size_t)plane * (size_t)(W * H);
    const float* px = x + pb + ic;
    const float* py = y + pb + ic;
    float* po = out + pb + (size_t)r0 * W + ic;     // ic == icr wherever stored

    // 3-deep register rings (rotated via unrolled STEP slot args)
    float hx[3], hy[3], hxy[3], hxx[3], hA[3], hB[3], xc[3];

    // Horizontal sums from 4 shuffles; hxy/hxx rebuilt from neighbors via FMA.
#define HQ(xv, yv, HX, HY, HXY, HXX) { \
    float xl = __shfl_up_sync(0xffffffffu, xv, 1); \
    float xr = __shfl_down_sync(0xffffffffu, xv, 1); \
    float yl = __shfl_up_sync(0xffffffffu, yv, 1); \
    float yr = __shfl_down_sync(0xffffffffu, yv, 1); \
    HX = xl + xv + xr; \
    HY = yl + yv + yr; \
    HXY = fmaf(xl, yl, fmaf(xr, yr, xv * yv)); \
    HXX = fmaf(xl, xl, fmaf(xr, xr, xv * xv)); }

#define ABROW(Sx, Sy, Sxy, Sxx, HA, HB) { \
    float mx = (Sx) * C9, my = (Sy) * C9; \
    float cov = fmaf((Sxy), C9, -(mx * my)); \
    float var = fmaf((Sxx), C9, fmaf(-mx, mx, EPSF)); \
    float Av = __fdividef(cov, var); \
    float Bv = fmaf(-Av, mx, my); \
    float Al = __shfl_up_sync(0xffffffffu, Av, 1); \
    float Ar = __shfl_down_sync(0xffffffffu, Av, 1); \
    float Bl = __shfl_up_sync(0xffffffffu, Bv, 1); \
    float Br = __shfl_down_sync(0xffffffffu, Bv, 1); \
    if (pl) { Al = Av; Bl = Bv; } \
    if (pr) { Ar = Av; Br = Bv; } \
    HA = Al + Av + Ar; \
    HB = Bl + Bv + Br; }

    // ---------------- prologue: rows r0-2 .. r0+1, A rows r0-1, r0 ----------------
    {
        float tx0, ty0, txy0, txx0, tx1, ty1, txy1, txx1;
        { int rc = max(r0 - 2, 0);
          float xv = px[(size_t)rc * W], yv = py[(size_t)rc * W];
          HQ(xv, yv, tx0, ty0, txy0, txx0) }
        { int rc = max(r0 - 1, 0);
          float xv = px[(size_t)rc * W], yv = py[(size_t)rc * W];
          HQ(xv, yv, tx1, ty1, txy1, txx1) }
        { float xv = px[(size_t)r0 * W], yv = py[(size_t)r0 * W];
          HQ(xv, yv, hx[0], hy[0], hxy[0], hxx[0]) xc[0] = xv; }
        { float xv = px[(size_t)(r0 + 1) * W], yv = py[(size_t)(r0 + 1) * W];
          HQ(xv, yv, hx[1], hy[1], hxy[1], hxx[1]) xc[1] = xv; }
        ABROW(tx0 + tx1 + hx[0], ty0 + ty1 + hy[0],
              txy0 + txy1 + hxy[0], txx0 + txx1 + hxx[0], hA[0], hB[0])
        ABROW(tx1 + hx[0] + hx[1], ty1 + hy[0] + hy[1],
              txy1 + hxy[0] + hxy[1], txx1 + hxx[0] + hxx[1], hA[1], hB[1])
        if (r0 == 0) { hA[0] = hA[1]; hB[0] = hB[1]; }   // top: A(-1) := A(0)
    }

    const float* pxr = px + (size_t)(r0 + 2) * W;
    const float* pyr = py + (size_t)(r0 + 2) * W;

    // Shared core of a step (everything after the input row is in registers).
#define CORE(ia, ib, ic2, xv, yv) \
    HQ(xv, yv, hx[ic2], hy[ic2], hxy[ic2], hxx[ic2]) \
    xc[ic2] = xv; \
    float hAn, hBn; \
    ABROW(hx[ia] + hx[ib] + hx[ic2], hy[ia] + hy[ib] + hy[ic2], \
          hxy[ia] + hxy[ib] + hxy[ic2], hxx[ia] + hxx[ib] + hxx[ic2], hAn, hBn)

#define TAIL(ia, ib, ic2) { \
    hA[ic2] = hAn; hB[ic2] = hBn; \
    float SA = hA[ia] + hA[ib] + hAn; \
    float SB = hB[ia] + hB[ib] + hBn; \
    float res = fmaf(SA * C9, xc[ia], SB * C9); \
    res = fminf(fmaxf(truncf(res), 0.0f), 255.0f); \
    if (do_store) *po = res; \
    po += W; }

    if (r0 < H - CHUNK_H) {
        // -------- interior chunks: guard-free hot loop --------
#define STEPC(ia, ib, ic2) { \
        float xv = *pxr, yv = *pyr; \
        pxr += W; pyr += W; \
        CORE(ia, ib, ic2, xv, yv) \
        TAIL(ia, ib, ic2) }

        for (int i = 0; i < CHUNK_H - 2; i += 3) {
            STEPC(0, 1, 2)
            STEPC(1, 2, 0)
            STEPC(2, 0, 1)
        }
        STEPC(0, 1, 2)
        STEPC(1, 2, 0)
#undef STEPC
    } else {
        // -------- last chunk: guarded loop (row replication at bottom) --------
#define STEPG(ia, ib, ic2, i) { \
        const int rr = r0 + (i); \
        float xv = *pxr, yv = *pyr; \
        if (rr + 2 < H - 1) { pxr += W; pyr += W; } \
        CORE(ia, ib, ic2, xv, yv) \
        if (rr + 1 >= H) { hAn = hA[ib]; hBn = hB[ib]; }  /* A(H):=A(H-1) */ \
        TAIL(ia, ib, ic2) }

        for (int i = 0; i < CHUNK_H - 2; i += 3) {
            STEPG(0, 1, 2, i)
            STEPG(1, 2, 0, i + 1)
            STEPG(2, 0, 1, i + 2)
        }
        STEPG(0, 1, 2, CHUNK_H - 2)
        STEPG(1, 2, 0, CHUNK_H - 1)
#undef STEPG
    }
#undef TAIL
#undef CORE
#undef ABROW
#undef HQ
}

extern "C" void kernel_launch(void* const* d_in, const int* in_sizes, int n_in,
                              void* d_out, int out_size) {
    const float* x = (const float*)d_in[0];
    const float* y = (const float*)d_in[1];
    float* out     = (float*)d_out;

    gf_kernel<<<NBLOCKS, 32 * WPB>>>(x, y, out);
}

// round 8
// speedup vs baseline: 1.9153x; 1.9153x over previous
#include <cuda_runtime.h>

// Guided filter, fully fused, SMEM-free warp-sliding implementation.
// EXACT round-2 skeleton (best: 88.8us). Single controlled delta: HQ uses
// 4 shuffles (x,y neighbors) + FMA rebuild of hxy/hxx instead of 8 shuffles
// of precomputed h-sums. Plus __launch_bounds__(256,6) to pin regs <= 40.

#define W 1024
#define H 1024
#define EPSF 1e-6f
#define C9 (1.0f / 9.0f)

#define OUT_COLS_PER_WARP 28
#define BANDS 37            // ceil(1024 / 28)
#define CHUNK_H 128
#define CHUNKS (H / CHUNK_H) // 8
#define WARPS_PER_BLOCK 8
#define UNITS (24 * BANDS * CHUNKS)                 // 7104 warps
#define NBLOCKS (UNITS / WARPS_PER_BLOCK)           // 888

__global__ __launch_bounds__(256, 6) void gf_kernel(const float* __restrict__ x,
                                                    const float* __restrict__ y,
                                                    float* __restrict__ out)
{
    const int wid  = threadIdx.x >> 5;
    const int lane = threadIdx.x & 31;
    const int g    = blockIdx.x * WARPS_PER_BLOCK + wid;

    const int plane = g / (BANDS * CHUNKS);
    const int rem   = g - plane * (BANDS * CHUNKS);
    const int band  = rem / CHUNKS;
    const int chunk = rem - band * CHUNKS;

    const int cbase = band * OUT_COLS_PER_WARP - 2;
    const int icr   = cbase + lane;                  // raw column of this lane
    const int ic    = min(max(icr, 0), W - 1);       // clamped load column
    const int r0    = chunk * CHUNK_H;

    const bool pl = (icr == 0);          // stage-2 left replication
    const bool pr = (icr == W - 1);      // stage-2 right replication
    const bool do_store = (lane >= 2) && (lane <= 29) && (icr >= 0) && (icr < W);

    const size_t pb = (size_t)plane * (W * H);
    const float* __restrict__ px = x + pb + ic;
    const float* __restrict__ py = y + pb + ic;
    float* po = out + pb + (size_t)r0 * W + ic;      // ic == icr wherever stored

    // register rings (rotated via unrolled STEP slots, never dynamically indexed)
    float hx[3], hy[3], hxy[3], hxx[3];   // horizontal sums of x, y, x*y, x*x
    float hA[3], hB[3];                   // horizontal sums of A, b
    float xc[3];                          // center x values

    // Horizontal sums from 4 shuffles; hxy/hxx rebuilt from neighbors via FMA.
#define HQ(xv, yv, HX, HY, HXY, HXX) { \
    float xl = __shfl_up_sync(0xffffffffu, xv, 1); \
    float xr = __shfl_down_sync(0xffffffffu, xv, 1); \
    float yl = __shfl_up_sync(0xffffffffu, yv, 1); \
    float yr = __shfl_down_sync(0xffffffffu, yv, 1); \
    HX = xl + xv + xr; \
    HY = yl + yv + yr; \
    HXY = fmaf(xl, yl, fmaf(xr, yr, xv * yv)); \
    HXX = fmaf(xl, xl, fmaf(xr, xr, xv * xv)); }

    // ---------------- prologue: fill rings for rows r0-2 .. r0+1 ----------------
    {
        float txx0, txy0, tx0, ty0, txx1, txy1, tx1, ty1;
        // row r0-2 (clamped at top)
        {
            int rc = max(r0 - 2, 0);
            float xv = px[(size_t)rc * W], yv = py[(size_t)rc * W];
            HQ(xv, yv, tx0, ty0, txy0, txx0)
        }
        // row r0-1
        {
            int rc = max(r0 - 1, 0);
            float xv = px[(size_t)rc * W], yv = py[(size_t)rc * W];
            HQ(xv, yv, tx1, ty1, txy1, txx1)
        }
        // row r0 -> slot 0
        {
            float xv = px[(size_t)r0 * W], yv = py[(size_t)r0 * W];
            HQ(xv, yv, hx[0], hy[0], hxy[0], hxx[0])
            xc[0] = xv;
        }
        // row r0+1 -> slot 1
        {
            float xv = px[(size_t)(r0 + 1) * W], yv = py[(size_t)(r0 + 1) * W];
            HQ(xv, yv, hx[1], hy[1], hxy[1], hxx[1])
            xc[1] = xv;
        }

        // A,b at row r0-1  (h rows r0-2, r0-1, r0)
        {
            float Sx = tx0 + tx1 + hx[0], Sy = ty0 + ty1 + hy[0];
            float Sxy = txy0 + txy1 + hxy[0], Sxx = txx0 + txx1 + hxx[0];
            float mx = Sx * C9, my = Sy * C9;
            float cov = fmaf(Sxy, C9, -(mx * my));
            float var = fmaf(Sxx, C9, fmaf(-mx, mx, EPSF));
            float Av = __fdividef(cov, var);
            float Bv = fmaf(-Av, mx, my);
            float Al = __shfl_up_sync(0xffffffffu, Av, 1);
            float Ar = __shfl_down_sync(0xffffffffu, Av, 1);
            float Bl = __shfl_up_sync(0xffffffffu, Bv, 1);
            float Br = __shfl_down_sync(0xffffffffu, Bv, 1);
            Al = pl ? Av : Al;  Bl = pl ? Bv : Bl;
            Ar = pr ? Av : Ar;  Br = pr ? Bv : Br;
            hA[0] = Al + Av + Ar;  hB[0] = Bl + Bv + Br;
        }
        // A,b at row r0  (h rows r0-1, r0, r0+1)
        {
            float Sx = tx1 + hx[0] + hx[1], Sy = ty1 + hy[0] + hy[1];
            float Sxy = txy1 + hxy[0] + hxy[1], Sxx = txx1 + hxx[0] + hxx[1];
            float mx = Sx * C9, my = Sy * C9;
            float cov = fmaf(Sxy, C9, -(mx * my));
            float var = fmaf(Sxx, C9, fmaf(-mx, mx, EPSF));
            float Av = __fdividef(cov, var);
            float Bv = fmaf(-Av, mx, my);
            float Al = __shfl_up_sync(0xffffffffu, Av, 1);
            float Ar = __shfl_down_sync(0xffffffffu, Av, 1);
            float Bl = __shfl_up_sync(0xffffffffu, Bv, 1);
            float Br = __shfl_down_sync(0xffffffffu, Bv, 1);
            Al = pl ? Av : Al;  Bl = pl ? Bv : Bl;
            Ar = pr ? Av : Ar;  Br = pr ? Bv : Br;
            hA[1] = Al + Av + Ar;  hB[1] = Bl + Bv + Br;
        }
        if (r0 == 0) {           // top replication: A row -1 := A row 0
            hA[0] = hA[1];
            hB[0] = hB[1];
        }
    }

    // pointers for the sliding loads (row r0+2 first; r0+2 <= 962 always valid)
    const float* pxr = px + (size_t)(r0 + 2) * W;
    const float* pyr = py + (size_t)(r0 + 2) * W;

    // One STEP produces output row rr = r0+i.
#define STEP(ia, ib, ic2, i) { \
        const int rr = r0 + (i); \
        float xv = *pxr, yv = *pyr; \
        if (rr + 2 < H - 1) { pxr += W; pyr += W; } \
        HQ(xv, yv, hx[ic2], hy[ic2], hxy[ic2], hxx[ic2]) \
        xc[ic2] = xv; \
        float Sx = hx[ia] + hx[ib] + hx[ic2]; \
        float Sy = hy[ia] + hy[ib] + hy[ic2]; \
        float Sxy = hxy[ia] + hxy[ib] + hxy[ic2]; \
        float Sxx = hxx[ia] + hxx[ib] + hxx[ic2]; \
        float mx = Sx * C9, my = Sy * C9; \
        float cov = fmaf(Sxy, C9, -(mx * my)); \
        float var = fmaf(Sxx, C9, fmaf(-mx, mx, EPSF)); \
        float Av = __fdividef(cov, var); \
        float Bv = fmaf(-Av, mx, my); \
        float Al = __shfl_up_sync(0xffffffffu, Av, 1); \
        float Ar = __shfl_down_sync(0xffffffffu, Av, 1); \
        float Bl = __shfl_up_sync(0xffffffffu, Bv, 1); \
        float Br = __shfl_down_sync(0xffffffffu, Bv, 1); \
        Al = pl ? Av : Al;  Bl = pl ? Bv : Bl; \
        Ar = pr ? Av : Ar;  Br = pr ? Bv : Br; \
        float hAn = Al + Av + Ar; \
        float hBn = Bl + Bv + Br; \
        if (rr + 1 >= H) { hAn = hA[ib]; hBn = hB[ib]; } /* bottom replication */ \
        hA[ic2] = hAn;  hB[ic2] = hBn; \
        float SA = hA[ia] + hA[ib] + hAn; \
        float SB = hB[ia] + hB[ib] + hBn; \
        float res = fmaf(SA * C9, xc[ia], SB * C9); \
        res = fminf(fmaxf(truncf(res), 0.0f), 255.0f); \
        if (do_store) *po = res; \
        po += W; \
    }

    // CHUNK_H = 128 rows: 42 triples (rows 0..125) + rows 126, 127
    for (int i = 0; i < CHUNK_H - 2; i += 3) {
        STEP(0, 1, 2, i)
        STEP(1, 2, 0, i + 1)
        STEP(2, 0, 1, i + 2)
    }
    STEP(0, 1, 2, CHUNK_H - 2)   // i = 126
    STEP(1, 2, 0, CHUNK_H - 1)   // i = 127
#undef STEP
#undef HQ
}

extern "C" void kernel_launch(void* const* d_in, const int* in_sizes, int n_in,
                              void* d_out, int out_size) {
    const float* x = (const float*)d_in[0];
    const float* y = (const float*)d_in[1];
    float* out     = (float*)d_out;

    gf_kernel<<<NBLOCKS, 32 * WARPS_PER_BLOCK>>>(x, y, out);
}

// round 9
// speedup vs baseline: 1.9783x; 1.0329x over previous
#include <cuda_runtime.h>

// Guided filter, fully fused, SMEM-free warp-sliding (round-8 skeleton, 85.4us).
// Deltas vs R8:
//  1. Guard peeling: steps i=0..122 run guard-free (no rr, no bounds ISETP/SEL,
//     unconditional pointer bumps); only the last 5 steps (i=123..127) carry
//     the bottom-row guards. Safe for every chunk: at i<=122, rr+2 <= 1020.
//  2. x9 algebra fold: A = (9*Sxy - Sx*Sy)/(9*Sxx - Sx^2 + 81*eps); b carried
//     9-scaled (Bv9 = Sy - A*Sx), unscaled once in the output FMA.
// Regs pinned via __launch_bounds__(256, 6).

#define W 1024
#define H 1024
#define EPS81 8.1e-5f           // 81 * 1e-6
#define C9 (1.0f / 9.0f)

#define OUT_COLS_PER_WARP 28
#define BANDS 37                // ceil(1024 / 28)
#define CHUNK_H 128
#define CHUNKS (H / CHUNK_H)    // 8
#define WARPS_PER_BLOCK 8
#define UNITS (24 * BANDS * CHUNKS)                 // 7104 warps
#define NBLOCKS (UNITS / WARPS_PER_BLOCK)           // 888

__global__ __launch_bounds__(256, 6) void gf_kernel(const float* __restrict__ x,
                                                    const float* __restrict__ y,
                                                    float* __restrict__ out)
{
    const int wid  = threadIdx.x >> 5;
    const int lane = threadIdx.x & 31;
    const int g    = blockIdx.x * WARPS_PER_BLOCK + wid;

    const int plane = g / (BANDS * CHUNKS);
    const int rem   = g - plane * (BANDS * CHUNKS);
    const int band  = rem / CHUNKS;
    const int chunk = rem - band * CHUNKS;

    const int cbase = band * OUT_COLS_PER_WARP - 2;
    const int icr   = cbase + lane;                  // raw column of this lane
    const int ic    = min(max(icr, 0), W - 1);       // clamped load column
    const int r0    = chunk * CHUNK_H;

    const bool pl = (icr == 0);          // stage-2 left replication
    const bool pr = (icr == W - 1);      // stage-2 right replication
    const bool do_store = (lane >= 2) && (lane <= 29) && (icr >= 0) && (icr < W);

    const size_t pb = (size_t)plane * (W * H);
    const float* __restrict__ px = x + pb + ic;
    const float* __restrict__ py = y + pb + ic;
    float* po = out + pb + (size_t)r0 * W + ic;      // ic == icr wherever stored

    // register rings (rotated via unrolled STEP slots, never dynamically indexed)
    float hx[3], hy[3], hxy[3], hxx[3];   // horizontal sums of x, y, x*y, x*x
    float hA[3], hB[3];                   // h-sums of A and 9*b
    float xc[3];                          // center x values

    // Horizontal sums from 4 shuffles; hxy/hxx rebuilt from neighbors via FMA.
#define HQ(xv, yv, HX, HY, HXY, HXX) { \
    float xl = __shfl_up_sync(0xffffffffu, xv, 1); \
    float xr = __shfl_down_sync(0xffffffffu, xv, 1); \
    float yl = __shfl_up_sync(0xffffffffu, yv, 1); \
    float yr = __shfl_down_sync(0xffffffffu, yv, 1); \
    HX = xl + xv + xr; \
    HY = yl + yv + yr; \
    HXY = fmaf(xl, yl, fmaf(xr, yr, xv * yv)); \
    HXX = fmaf(xl, xl, fmaf(xr, xr, xv * xv)); }

    // A,b9 from 3x3 sums: A = (9*Sxy - Sx*Sy)/(9*Sxx - Sx^2 + 81e), b9 = Sy - A*Sx
#define ABROW(Sx, Sy, Sxy, Sxx, HA, HB) { \
    float t   = (Sx) * (Sy); \
    float num = fmaf((Sxy), 9.0f, -t); \
    float u   = fmaf(-(Sx), (Sx), EPS81); \
    float den = fmaf((Sxx), 9.0f, u); \
    float Av  = __fdividef(num, den); \
    float Bv  = fmaf(-Av, (Sx), (Sy)); \
    float Al = __shfl_up_sync(0xffffffffu, Av, 1); \
    float Ar = __shfl_down_sync(0xffffffffu, Av, 1); \
    float Bl = __shfl_up_sync(0xffffffffu, Bv, 1); \
    float Br = __shfl_down_sync(0xffffffffu, Bv, 1); \
    Al = pl ? Av : Al;  Bl = pl ? Bv : Bl; \
    Ar = pr ? Av : Ar;  Br = pr ? Bv : Br; \
    HA = Al + Av + Ar; \
    HB = Bl + Bv + Br; }

    // ---------------- prologue: fill rings for rows r0-2 .. r0+1 ----------------
    {
        float txx0, txy0, tx0, ty0, txx1, txy1, tx1, ty1;
        { int rc = max(r0 - 2, 0);
          float xv = px[(size_t)rc * W], yv = py[(size_t)rc * W];
          HQ(xv, yv, tx0, ty0, txy0, txx0) }
        { int rc = max(r0 - 1, 0);
          float xv = px[(size_t)rc * W], yv = py[(size_t)rc * W];
          HQ(xv, yv, tx1, ty1, txy1, txx1) }
        { float xv = px[(size_t)r0 * W], yv = py[(size_t)r0 * W];
          HQ(xv, yv, hx[0], hy[0], hxy[0], hxx[0]) xc[0] = xv; }
        { float xv = px[(size_t)(r0 + 1) * W], yv = py[(size_t)(r0 + 1) * W];
          HQ(xv, yv, hx[1], hy[1], hxy[1], hxx[1]) xc[1] = xv; }
        ABROW(tx0 + tx1 + hx[0], ty0 + ty1 + hy[0],
              txy0 + txy1 + hxy[0], txx0 + txx1 + hxx[0], hA[0], hB[0])
        ABROW(tx1 + hx[0] + hx[1], ty1 + hy[0] + hy[1],
              txy1 + hxy[0] + hxy[1], txx1 + hxx[0] + hxx[1], hA[1], hB[1])
        if (r0 == 0) { hA[0] = hA[1]; hB[0] = hB[1]; }   // top: A(-1) := A(0)
    }

    // pointers for the sliding loads (first load is row r0+2)
    const float* pxr = px + (size_t)(r0 + 2) * W;
    const float* pyr = py + (size_t)(r0 + 2) * W;

    // Common core after the input row is in registers.
#define SCORE(ia, ib, ic2, xv, yv) \
    HQ(xv, yv, hx[ic2], hy[ic2], hxy[ic2], hxx[ic2]) \
    xc[ic2] = xv; \
    float hAn, hBn; \
    ABROW(hx[ia] + hx[ib] + hx[ic2], hy[ia] + hy[ib] + hy[ic2], \
          hxy[ia] + hxy[ib] + hxy[ic2], hxx[ia] + hxx[ib] + hxx[ic2], hAn, hBn)

#define STAIL(ia, ib, ic2) \
    hA[ic2] = hAn;  hB[ic2] = hBn; \
    float SA = hA[ia] + hA[ib] + hAn; \
    float SB = hB[ia] + hB[ib] + hBn; \
    float res = fmaf(SA, xc[ia], SB * C9) * C9; \
    res = fminf(fmaxf(truncf(res), 0.0f), 255.0f); \
    if (do_store) *po = res; \
    po += W;

    // Guard-free step (valid whenever rr+2 < H-1 and rr+1 < H; true for i<=122)
#define STEP_F(ia, ib, ic2) { \
        float xv = *pxr, yv = *pyr; \
        pxr += W; pyr += W; \
        SCORE(ia, ib, ic2, xv, yv) \
        STAIL(ia, ib, ic2) }

    // Guarded step (bottom-of-image handling, identical semantics to R8)
#define STEP_G(ia, ib, ic2, i) { \
        const int rr = r0 + (i); \
        float xv = *pxr, yv = *pyr; \
        if (rr + 2 < H - 1) { pxr += W; pyr += W; } \
        SCORE(ia, ib, ic2, xv, yv) \
        if (rr + 1 >= H) { hAn = hA[ib]; hBn = hB[ib]; } /* A(H):=A(H-1) */ \
        STAIL(ia, ib, ic2) }

    // 41 guard-free triples (i = 0..122), then 5 guarded steps (i = 123..127)
    for (int i = 0; i < 123; i += 3) {
        STEP_F(0, 1, 2)
        STEP_F(1, 2, 0)
        STEP_F(2, 0, 1)
    }
    STEP_G(0, 1, 2, 123)
    STEP_G(1, 2, 0, 124)
    STEP_G(2, 0, 1, 125)
    STEP_G(0, 1, 2, 126)
    STEP_G(1, 2, 0, 127)
#undef STEP_G
#undef STEP_F
#undef STAIL
#undef SCORE
#undef ABROW
#undef HQ
}

extern "C" void kernel_launch(void* const* d_in, const int* in_sizes, int n_in,
                              void* d_out, int out_size) {
    const float* x = (const float*)d_in[0];
    const float* y = (const float*)d_in[1];
    float* out     = (float*)d_out;

    gf_kernel<<<NBLOCKS, 32 * WARPS_PER_BLOCK>>>(x, y, out);
}